// round 15
// baseline (speedup 1.0000x reference)
#include <cuda_runtime.h>
#include <cuda_fp16.h>
#include <math.h>
#include <stdint.h>

// Problem constants
#define B_    4
#define N_    4096
#define DIM_  1024
#define H_    16
#define DH_   64
#define M_    32
#define R_    16384            // B_*N_ rows

// feature-map constants
#define NORMALIZER   0.35355339059327379f   // 64^-0.25
#define HALF_NORM2   0.0625f                // 0.5 * normalizer^2
#define RATIO        0.17677669529663689f   // 32^-0.5
#define EPS_         1e-4f

// f32 scratch (floats)
#define OFF_V    ((size_t)33554432)
#define OFF_QF   ((size_t)67108864)
#define OFF_TK   ((size_t)75497472)
#define OFF_CTX  ((size_t)83886080)
#define OFF_KCS  ((size_t)84017152)
#define OFF_KMAX ((size_t)84019200)
#define SCRATCH_FLOATS ((size_t)84019264)
__device__ float g_scratch[SCRATCH_FLOATS];

// fp16 split scratch (halves), PRE-TILED layout:
// element (row R, k) lives at chunk ((R>>7)*32 + (k>>5)) * 5120
//                    + (R&127)*40 + (k&31)
#define CHUNK_H  5120
#define RBLK_H   (32 * CHUNK_H)          // 163840 halves per 128-row block
#define A_HALVES ((size_t)128 * RBLK_H)
#define W_HALVES ((size_t)8 * RBLK_H)
#define HX_HI ((size_t)0)
#define HX_LO ((size_t)20971520)
#define HA_HI ((size_t)41943040)
#define HA_LO ((size_t)62914560)
#define HW_BASE ((size_t)83886080)       // 8 x W_HALVES
#define HALF_COUNT ((size_t)94371840)
__device__ __half g_half[HALF_COUNT];

// ---------------------------------------------------------------------------
// PTX helpers
// ---------------------------------------------------------------------------
__device__ __forceinline__ uint32_t smem_u32(const void* p) {
    uint32_t a;
    asm("{ .reg .u64 t; cvta.to.shared.u64 t, %1; cvt.u32.u64 %0, t; }"
        : "=r"(a) : "l"(p));
    return a;
}
#define MBAR_INIT(mb, c) \
    asm volatile("mbarrier.init.shared.b64 [%0], %1;" \
                 :: "r"((uint32_t)(mb)), "r"((uint32_t)(c)) : "memory")
#define MBAR_EXPECT_TX(mb, bytes) \
    asm volatile("mbarrier.arrive.expect_tx.shared.b64 _, [%0], %1;" \
                 :: "r"((uint32_t)(mb)), "r"((uint32_t)(bytes)) : "memory")
#define MBAR_WAIT(mb, ph) do { \
    uint32_t _mb = (uint32_t)(mb), _ph = (uint32_t)(ph); \
    asm volatile( \
        "{\n\t.reg .pred P1;\n\t" \
        "WL_%=:\n\t" \
        "mbarrier.try_wait.parity.acquire.cta.shared::cta.b64 P1, [%0], %1, 0x989680;\n\t" \
        "@P1 bra.uni WD_%=;\n\t" \
        "bra.uni WL_%=;\n\t" \
        "WD_%=:\n\t}" :: "r"(_mb), "r"(_ph) : "memory"); \
} while (0)
#define BULK_LD(dst, src, bytes, mb) \
    asm volatile("cp.async.bulk.shared::cluster.global.mbarrier::complete_tx::bytes " \
                 "[%0], [%1], %2, [%3];" \
                 :: "r"((uint32_t)(dst)), "l"(src), "r"((uint32_t)(bytes)), \
                    "r"((uint32_t)(mb)) : "memory")

// ---------------------------------------------------------------------------
// init small accumulators
// ---------------------------------------------------------------------------
__global__ void init_kernel() {
    int i = blockIdx.x * blockDim.x + threadIdx.x;
    if (i < 131072) g_scratch[OFF_CTX + i] = 0.0f;
    if (i < 2048)   g_scratch[OFF_KCS + i] = 0.0f;
    if (i < 64)     g_scratch[OFF_KMAX + i] = -INFINITY;
}

// ---------------------------------------------------------------------------
// tiled offset helper
// ---------------------------------------------------------------------------
__device__ __forceinline__ size_t tiled_off(int R, int k) {
    return (size_t)((R >> 7) * 32 + (k >> 5)) * CHUNK_H + (R & 127) * 40 +
           (k & 31);
}

// ---------------------------------------------------------------------------
// fp16 split into tiled layout (4 elements per thread, same chunk)
// ---------------------------------------------------------------------------
__global__ void split_kernel(const float* __restrict__ s, __half* __restrict__ hi,
                             __half* __restrict__ lo, int n) {
    int i = (blockIdx.x * blockDim.x + threadIdx.x) * 4;
    if (i >= n) return;
    float4 v = *(const float4*)(s + i);
    float vv[4] = {v.x, v.y, v.z, v.w};
    __half h[4], l[4];
#pragma unroll
    for (int j = 0; j < 4; j++) {
        h[j] = __float2half_rn(vv[j]);
        l[j] = __float2half_rn(vv[j] - __half2float(h[j]));
    }
    int R = i >> 10, k = i & 1023;
    size_t off = tiled_off(R, k);
    __half2* hp = (__half2*)(hi + off);
    hp[0] = __halves2half2(h[0], h[1]);
    hp[1] = __halves2half2(h[2], h[3]);
    __half2* lp = (__half2*)(lo + off);
    lp[0] = __halves2half2(l[0], l[1]);
    lp[1] = __halves2half2(l[2], l[3]);
}

// fp16 split + transpose for weights: W[k][n] -> tiled[n][k]
__global__ void splitT_kernel(const float* __restrict__ W, __half* __restrict__ hiT,
                              __half* __restrict__ loT) {
    __shared__ float t[32][33];
    int tx = threadIdx.x, ty = threadIdx.y;
    int bn = blockIdx.x * 32, bk = blockIdx.y * 32;
    for (int j = ty; j < 32; j += 8)
        t[j][tx] = W[(size_t)(bk + j) * DIM_ + bn + tx];
    __syncthreads();
    for (int j = ty; j < 32; j += 8) {
        float v = t[tx][j];
        __half h = __float2half_rn(v);
        __half l = __float2half_rn(v - __half2float(h));
        size_t off = tiled_off(bn + j, bk + tx);
        hiT[off] = h;
        loT[off] = l;
    }
}

// ---------------------------------------------------------------------------
// fp16 HMMA m16n8k16 wrapper
// ---------------------------------------------------------------------------
__device__ __forceinline__ void mma_f16(float* c, const uint32_t* a,
                                        uint32_t b0, uint32_t b1) {
    asm volatile(
        "mma.sync.aligned.m16n8k16.row.col.f32.f16.f16.f32 "
        "{%0,%1,%2,%3}, {%4,%5,%6,%7}, {%8,%9}, {%0,%1,%2,%3};"
        : "+f"(c[0]), "+f"(c[1]), "+f"(c[2]), "+f"(c[3])
        : "r"(a[0]), "r"(a[1]), "r"(a[2]), "r"(a[3]), "r"(b0), "r"(b1));
}

// ---------------------------------------------------------------------------
// atomic float max via CAS
// ---------------------------------------------------------------------------
__device__ __forceinline__ void atomicMaxFloat(float* addr, float val) {
    int old = __float_as_int(*addr);
    while (__int_as_float(old) < val) {
        int assumed = old;
        old = atomicCAS((int*)addr, assumed, __float_as_int(val));
        if (old == assumed) break;
    }
}

// ---------------------------------------------------------------------------
// HMMA GEMM, cp.async.bulk 3-stage pipeline (4 bulk ops/stage) +
// optional fused Performer feature epilogue.
// MODE 0: C = A@W + bias -> out (fp32, R x 1024)
// MODE 1: q-feature epilogue -> out = QF[(bh*N+n)*32+m]
// MODE 2: k-feature epilogue -> out = TK (dd - diag); atomicMax kmax_g[bh]
// ---------------------------------------------------------------------------
#define TILE_H   5120                  // halves per tile (128*40)
#define TILE_B2  (TILE_H * 2)          // bytes per tile (10240)
#define STAGE_H  (4 * TILE_H)          // halves per stage
#define STAGE_B  (STAGE_H * 2)         // bytes per stage (40960)
#define NPIPE    3
#define SMEM0    (NPIPE * STAGE_B)             // 122880
#define SMEM_F   (NPIPE * STAGE_B + 8704)      // + projS 32*68 floats
#define NST 32                         // K / BK

template <int MODE>
__global__ void __launch_bounds__(256)
gemm_hmma_kernel(const __half* __restrict__ Ahi, const __half* __restrict__ Alo,
                 const __half* __restrict__ Bhi, const __half* __restrict__ Blo,
                 const float* __restrict__ bias, float* __restrict__ out,
                 const float* __restrict__ proj, float* __restrict__ kmax_g) {
    extern __shared__ __align__(16) __half sm[];
    const uint32_t smb = smem_u32(sm);
    __shared__ __align__(8) uint64_t mbars[NPIPE];
    __shared__ float s_hm[8];
    const uint32_t mbb = smem_u32(&mbars[0]);

    const int tid = threadIdx.x;
    const int lane = tid & 31, wid = tid >> 5;
    const int wm = wid & 3;            // warp m index (x32 rows)
    const int wn = wid >> 2;           // warp n index (x64 cols)
    const int m0 = blockIdx.y * 128, n0 = blockIdx.x * 128;
    const int grp = lane >> 2;         // 0..7
    const int tig = lane & 3;          // 0..3

    const size_t aBase = (size_t)(m0 >> 7) * RBLK_H;
    const size_t bBase = (size_t)(n0 >> 7) * RBLK_H;

    float* projS = (float*)(sm + NPIPE * STAGE_H);   // [m][d] stride 68
    if (MODE != 0) {
        for (int i = tid; i < 2048; i += 256) {
            int mrow = i >> 6, d = i & 63;
            projS[mrow * 68 + d] = proj[i];
        }
    }

    if (tid == 0) {
#pragma unroll
        for (int p = 0; p < NPIPE; p++) MBAR_INIT(mbb + p * 8, 1);
    }
    __syncthreads();

    float acc[2][8][4];
#pragma unroll
    for (int mi = 0; mi < 2; mi++)
#pragma unroll
        for (int ni = 0; ni < 8; ni++)
#pragma unroll
            for (int j = 0; j < 4; j++) acc[mi][ni][j] = 0.0f;

    auto issue_stage = [&](int s) {
        if (tid == 0) {
            int sb = s % NPIPE;
            uint32_t mb = mbb + sb * 8;
            MBAR_EXPECT_TX(mb, STAGE_B);
            uint32_t d = smb + sb * STAGE_B;
            size_t co = (size_t)s * CHUNK_H;
            BULK_LD(d, Ahi + aBase + co, TILE_B2, mb);
            BULK_LD(d + TILE_B2, Alo + aBase + co, TILE_B2, mb);
            BULK_LD(d + 2 * TILE_B2, Bhi + bBase + co, TILE_B2, mb);
            BULK_LD(d + 3 * TILE_B2, Blo + bBase + co, TILE_B2, mb);
        }
    };

    issue_stage(0);
    issue_stage(1);

    for (int s = 0; s < NST; s++) {
        if (s + 2 < NST) issue_stage(s + 2);
        int sb = s % NPIPE;
        MBAR_WAIT(mbb + sb * 8, (s / NPIPE) & 1);

        const uint32_t* wAh = (const uint32_t*)(sm + sb * STAGE_H);
        const uint32_t* wAl = wAh + TILE_H / 2;
        const uint32_t* wBh = wAh + TILE_H;
        const uint32_t* wBl = wAh + 3 * TILE_H / 2;

#pragma unroll
        for (int ks = 0; ks < 2; ks++) {
            const int kw = ks * 8 + tig;
            uint32_t ah[2][4], al[2][4];
#pragma unroll
            for (int mi = 0; mi < 2; mi++) {
                int rr = wm * 32 + mi * 16 + grp;
                ah[mi][0] = wAh[rr * 20 + kw];
                ah[mi][1] = wAh[(rr + 8) * 20 + kw];
                ah[mi][2] = wAh[rr * 20 + kw + 4];
                ah[mi][3] = wAh[(rr + 8) * 20 + kw + 4];
                al[mi][0] = wAl[rr * 20 + kw];
                al[mi][1] = wAl[(rr + 8) * 20 + kw];
                al[mi][2] = wAl[rr * 20 + kw + 4];
                al[mi][3] = wAl[(rr + 8) * 20 + kw + 4];
            }
#pragma unroll
            for (int nj = 0; nj < 8; nj++) {
                int cc = wn * 64 + nj * 8 + grp;
                uint32_t bh0 = wBh[cc * 20 + kw];
                uint32_t bh1 = wBh[cc * 20 + kw + 4];
                uint32_t bl0 = wBl[cc * 20 + kw];
                uint32_t bl1 = wBl[cc * 20 + kw + 4];
#pragma unroll
                for (int mi = 0; mi < 2; mi++) {
                    mma_f16(acc[mi][nj], ah[mi], bh0, bh1);
                    mma_f16(acc[mi][nj], ah[mi], bl0, bl1);
                    mma_f16(acc[mi][nj], al[mi], bh0, bh1);
                }
            }
        }
        __syncthreads();
    }

    if (MODE == 0) {
#pragma unroll
        for (int ni = 0; ni < 8; ni++) {
            int col = n0 + wn * 64 + ni * 8 + tig * 2;
            float2 bv = *(const float2*)&bias[col];
#pragma unroll
            for (int mi = 0; mi < 2; mi++) {
                int row = m0 + wm * 32 + mi * 16 + grp;
                float2 c0 = make_float2(acc[mi][ni][0] + bv.x,
                                        acc[mi][ni][1] + bv.y);
                float2 c1 = make_float2(acc[mi][ni][2] + bv.x,
                                        acc[mi][ni][3] + bv.y);
                *(float2*)&out[(size_t)row * DIM_ + col] = c0;
                *(float2*)&out[(size_t)(row + 8) * DIM_ + col] = c1;
            }
        }
        return;
    }

    // -------- fused feature epilogue (MODE 1 = q, MODE 2 = k) --------
    float* Cs = (float*)sm;   // 128 x 132 fp32 tile, reuses stage area
#pragma unroll
    for (int ni = 0; ni < 8; ni++) {
        int col = wn * 64 + ni * 8 + tig * 2;
        float2 bv = *(const float2*)&bias[n0 + col];
#pragma unroll
        for (int mi = 0; mi < 2; mi++) {
            int row = wm * 32 + mi * 16 + grp;
            Cs[row * 132 + col] = acc[mi][ni][0] + bv.x;
            Cs[row * 132 + col + 1] = acc[mi][ni][1] + bv.y;
            Cs[(row + 8) * 132 + col] = acc[mi][ni][2] + bv.x;
            Cs[(row + 8) * 132 + col + 1] = acc[mi][ni][3] + bv.y;
        }
    }
    __syncthreads();

    const int hh = wid & 1;                    // head within tile
    const int head = blockIdx.x * 2 + hh;      // global head
    const int b = m0 >> 12;                    // batch (constant per block)
    const int bh = b * H_ + head;
    const int r0 = (wid >> 1) * 32;            // 4 warp-groups x 32 rows
    const float4* pr = (const float4*)&projS[lane * 68];
    float kmaxw = -INFINITY;

    for (int rr = r0; rr < r0 + 32; rr++) {
        const float* qrow = &Cs[rr * 132 + hh * 64];
        float q0 = qrow[lane], q1 = qrow[lane + 32];
        float ss = fmaf(q0, q0, q1 * q1);
#pragma unroll
        for (int off = 16; off > 0; off >>= 1)
            ss += __shfl_xor_sync(0xffffffffu, ss, off);

        const float4* qp = (const float4*)qrow;
        float accd = 0.0f;
#pragma unroll
        for (int d4 = 0; d4 < 16; d4++) {
            float4 p = pr[d4];
            float4 qd = qp[d4];
            accd = fmaf(p.x, qd.x, accd);
            accd = fmaf(p.y, qd.y, accd);
            accd = fmaf(p.z, qd.z, accd);
            accd = fmaf(p.w, qd.w, accd);
        }
        float dd = NORMALIZER * accd;          // data_dash at m = lane
        float diag = HALF_NORM2 * ss;

        float wmax = dd;
#pragma unroll
        for (int off = 16; off > 0; off >>= 1)
            wmax = fmaxf(wmax, __shfl_xor_sync(0xffffffffu, wmax, off));

        const int n = (m0 + rr) & 4095;
        const size_t idx = ((size_t)bh * N_ + n) * M_ + lane;
        if (MODE == 1) {
            out[idx] = RATIO * (__expf(dd - diag - wmax) + EPS_);
        } else {
            out[idx] = dd - diag;
            kmaxw = fmaxf(kmaxw, wmax);
        }
    }

    if (MODE == 2) {
        if (lane == 0) s_hm[wid] = kmaxw;
        __syncthreads();
        if (tid < 2) {
            float m4 = fmaxf(fmaxf(s_hm[tid], s_hm[tid + 2]),
                             fmaxf(s_hm[tid + 4], s_hm[tid + 6]));
            atomicMaxFloat(&kmax_g[b * H_ + blockIdx.x * 2 + tid], m4);
        }
    }
}

// ---------------------------------------------------------------------------
// Context + k_cumsum (__expf in hot loop)
// ---------------------------------------------------------------------------
__global__ void __launch_bounds__(256)
ctx_kernel(const unsigned char* __restrict__ mask) {
    __shared__ __align__(16) float kf_s[16][32];
    __shared__ __align__(16) float v_s[16][64];
    const int tid = threadIdx.x;
    const int bh = blockIdx.x >> 3, chunk = blockIdx.x & 7;
    const int b = bh >> 4, h = bh & 15;
    const float kmax = g_scratch[OFF_KMAX + bh];
    const int m = tid >> 3, eb = (tid & 7) * 8;

    float acc[8];
#pragma unroll
    for (int j = 0; j < 8; j++) acc[j] = 0.0f;
    float kcsl = 0.0f;

    const float* tk = g_scratch + OFF_TK + (size_t)bh * N_ * M_;
    const float* V = g_scratch + OFF_V;

    const int base = chunk * 512;
    for (int t0 = base; t0 < base + 512; t0 += 16) {
#pragma unroll
        for (int j = 0; j < 2; j++) {
            int lin = tid * 2 + j;
            int i = lin >> 5, mm = lin & 31;
            float tv = tk[(size_t)(t0 + i) * M_ + mm];
            kf_s[i][mm] = RATIO * (__expf(tv - kmax) + EPS_);
        }
        {
            int i = tid >> 4, e4 = (tid & 15) * 4;
            int n = t0 + i;
            float4 v4 =
                *(const float4*)&V[(size_t)(b * N_ + n) * DIM_ + h * DH_ + e4];
            if (mask[b * N_ + n]) v4 = make_float4(0.f, 0.f, 0.f, 0.f);
            *(float4*)&v_s[i][e4] = v4;
        }
        __syncthreads();
#pragma unroll
        for (int i = 0; i < 16; i++) {
            float kfm = kf_s[i][m];
            kcsl += kfm;
#pragma unroll
            for (int j = 0; j < 8; j++)
                acc[j] = fmaf(kfm, v_s[i][eb + j], acc[j]);
        }
        __syncthreads();
    }

    float* ctx = g_scratch + OFF_CTX + (size_t)bh * (M_ * DH_);
#pragma unroll
    for (int j = 0; j < 8; j++) atomicAdd(&ctx[m * DH_ + eb + j], acc[j]);
    if ((tid & 7) == 0) atomicAdd(&g_scratch[OFF_KCS + bh * M_ + m], kcsl);
}

// ---------------------------------------------------------------------------
// Output head: smem broadcast (no shfl chain); writes fp16 hi/lo tiled
// ---------------------------------------------------------------------------
__global__ void __launch_bounds__(256)
outhead_kernel(__half* __restrict__ Ohi, __half* __restrict__ Olo) {
    __shared__ float ctx_s[M_ * DH_];
    __shared__ float kcs_s[M_];
    __shared__ float qs[256];
    const int tid = threadIdx.x;
    const int bh = blockIdx.x >> 3, chunk = blockIdx.x & 7;
    const int b = bh >> 4, h = bh & 15;
    for (int i = tid; i < M_ * DH_; i += 256)
        ctx_s[i] = g_scratch[OFF_CTX + (size_t)bh * (M_ * DH_) + i];
    if (tid < M_) kcs_s[tid] = g_scratch[OFF_KCS + bh * M_ + tid];
    __syncthreads();

    const int w = tid >> 5, lane = tid & 31;
    float* qw = &qs[w * 32];
    const float* qf = g_scratch + OFF_QF + (size_t)bh * N_ * M_;

    for (int rr = 0; rr < 64; rr++) {
        int n = chunk * 512 + w * 64 + rr;
        qw[lane] = qf[(size_t)n * M_ + lane];
        __syncwarp();
        float acc0 = 0.0f, acc1 = 0.0f, den = 0.0f;
#pragma unroll
        for (int mm = 0; mm < 32; mm++) {
            float qm = qw[mm];
            acc0 = fmaf(qm, ctx_s[mm * DH_ + lane], acc0);
            acc1 = fmaf(qm, ctx_s[mm * DH_ + 32 + lane], acc1);
            den = fmaf(qm, kcs_s[mm], den);
        }
        __syncwarp();
        float dinv = 1.0f / den;
        float v0 = acc0 * dinv, v1 = acc1 * dinv;
        __half h0 = __float2half_rn(v0);
        __half h1 = __float2half_rn(v1);
        __half l0 = __float2half_rn(v0 - __half2float(h0));
        __half l1 = __float2half_rn(v1 - __half2float(h1));
        int R = b * N_ + n;
        size_t o1 = tiled_off(R, h * DH_ + lane);
        size_t o2 = tiled_off(R, h * DH_ + 32 + lane);
        Ohi[o1] = h0;
        Ohi[o2] = h1;
        Olo[o1] = l0;
        Olo[o2] = l1;
    }
}

// ---------------------------------------------------------------------------
// launch
// ---------------------------------------------------------------------------
extern "C" void kernel_launch(void* const* d_in, const int* in_sizes, int n_in,
                              void* d_out, int out_size) {
    (void)in_sizes; (void)n_in; (void)out_size;
    const float* x = (const float*)d_in[0];
    const unsigned char* mask = (const unsigned char*)d_in[1];
    const float* proj = (const float*)d_in[2];
    const float* Wq = (const float*)d_in[3];
    const float* bq = (const float*)d_in[4];
    const float* Wk = (const float*)d_in[5];
    const float* bk = (const float*)d_in[6];
    const float* Wv = (const float*)d_in[7];
    const float* bv = (const float*)d_in[8];
    const float* Wo = (const float*)d_in[9];
    const float* bo = (const float*)d_in[10];

    float* scratch = nullptr;
    cudaGetSymbolAddress((void**)&scratch, g_scratch);
    __half* hs = nullptr;
    cudaGetSymbolAddress((void**)&hs, g_half);

    cudaFuncSetAttribute(gemm_hmma_kernel<0>,
                         cudaFuncAttributeMaxDynamicSharedMemorySize, SMEM0);
    cudaFuncSetAttribute(gemm_hmma_kernel<1>,
                         cudaFuncAttributeMaxDynamicSharedMemorySize, SMEM_F);
    cudaFuncSetAttribute(gemm_hmma_kernel<2>,
                         cudaFuncAttributeMaxDynamicSharedMemorySize, SMEM_F);

    dim3 tg(32, 32), tb(32, 8);
    dim3 gg(DIM_ / 128, R_ / 128);   // (8, 128)

    init_kernel<<<512, 256>>>();
    split_kernel<<<R_ * DIM_ / 4 / 256, 256>>>(x, hs + HX_HI,
                                               hs + HX_LO, R_ * DIM_);
    splitT_kernel<<<tg, tb>>>(Wq, hs + HW_BASE + 0 * W_HALVES,
                              hs + HW_BASE + 1 * W_HALVES);
    splitT_kernel<<<tg, tb>>>(Wk, hs + HW_BASE + 2 * W_HALVES,
                              hs + HW_BASE + 3 * W_HALVES);
    splitT_kernel<<<tg, tb>>>(Wv, hs + HW_BASE + 4 * W_HALVES,
                              hs + HW_BASE + 5 * W_HALVES);

    // Q GEMM + fused q-feature
    gemm_hmma_kernel<1><<<gg, 256, SMEM_F>>>(
        hs + HX_HI, hs + HX_LO, hs + HW_BASE + 0 * W_HALVES,
        hs + HW_BASE + 1 * W_HALVES, bq, scratch + OFF_QF, proj, nullptr);
    // K GEMM + fused k-feature
    gemm_hmma_kernel<2><<<gg, 256, SMEM_F>>>(
        hs + HX_HI, hs + HX_LO, hs + HW_BASE + 2 * W_HALVES,
        hs + HW_BASE + 3 * W_HALVES, bk, scratch + OFF_TK, proj,
        scratch + OFF_KMAX);
    // V GEMM (plain)
    gemm_hmma_kernel<0><<<gg, 256, SMEM0>>>(
        hs + HX_HI, hs + HX_LO, hs + HW_BASE + 4 * W_HALVES,
        hs + HW_BASE + 5 * W_HALVES, bv, scratch + OFF_V, nullptr, nullptr);

    ctx_kernel<<<64 * 8, 256>>>(mask);
    outhead_kernel<<<64 * 8, 256>>>(hs + HA_HI, hs + HA_LO);

    splitT_kernel<<<tg, tb>>>(Wo, hs + HW_BASE + 6 * W_HALVES,
                              hs + HW_BASE + 7 * W_HALVES);
    // O GEMM (plain) -> d_out
    gemm_hmma_kernel<0><<<gg, 256, SMEM0>>>(
        hs + HA_HI, hs + HA_LO, hs + HW_BASE + 6 * W_HALVES,
        hs + HW_BASE + 7 * W_HALVES, bo, (float*)d_out, nullptr, nullptr);
}

// round 16
// speedup vs baseline: 1.1634x; 1.1634x over previous
#include <cuda_runtime.h>
#include <cuda_fp16.h>
#include <math.h>
#include <stdint.h>

// Problem constants
#define B_    4
#define N_    4096
#define DIM_  1024
#define H_    16
#define DH_   64
#define M_    32
#define R_    16384            // B_*N_ rows

// feature-map constants
#define NORMALIZER   0.35355339059327379f   // 64^-0.25
#define HALF_NORM2   0.0625f                // 0.5 * normalizer^2
#define RATIO        0.17677669529663689f   // 32^-0.5
#define EPS_         1e-4f

// f32 scratch (floats)
#define OFF_V    ((size_t)33554432)
#define OFF_QF   ((size_t)67108864)
#define OFF_TK   ((size_t)75497472)
#define OFF_CTX  ((size_t)83886080)
#define OFF_KCS  ((size_t)84017152)
#define OFF_KMAX ((size_t)84019200)
#define SCRATCH_FLOATS ((size_t)84019264)
__device__ float g_scratch[SCRATCH_FLOATS];

// fp16 split scratch (halves), PRE-TILED layout:
// element (row R, k) lives at chunk ((R>>7)*32 + (k>>5)) * 5120
//                    + (R&127)*40 + (k&31)
#define CHUNK_H  5120
#define RBLK_H   (32 * CHUNK_H)          // 163840 halves per 128-row block
#define A_HALVES ((size_t)128 * RBLK_H)
#define W_HALVES ((size_t)8 * RBLK_H)
#define HX_HI ((size_t)0)
#define HX_LO ((size_t)20971520)
#define HA_HI ((size_t)41943040)
#define HA_LO ((size_t)62914560)
#define HW_BASE ((size_t)83886080)       // 8 x W_HALVES
#define HALF_COUNT ((size_t)94371840)
__device__ __half g_half[HALF_COUNT];

// ---------------------------------------------------------------------------
// PTX helpers
// ---------------------------------------------------------------------------
__device__ __forceinline__ uint32_t smem_u32(const void* p) {
    uint32_t a;
    asm("{ .reg .u64 t; cvta.to.shared.u64 t, %1; cvt.u32.u64 %0, t; }"
        : "=r"(a) : "l"(p));
    return a;
}
#define MBAR_INIT(mb, c) \
    asm volatile("mbarrier.init.shared.b64 [%0], %1;" \
                 :: "r"((uint32_t)(mb)), "r"((uint32_t)(c)) : "memory")
#define MBAR_EXPECT_TX(mb, bytes) \
    asm volatile("mbarrier.arrive.expect_tx.shared.b64 _, [%0], %1;" \
                 :: "r"((uint32_t)(mb)), "r"((uint32_t)(bytes)) : "memory")
#define MBAR_WAIT(mb, ph) do { \
    uint32_t _mb = (uint32_t)(mb), _ph = (uint32_t)(ph); \
    asm volatile( \
        "{\n\t.reg .pred P1;\n\t" \
        "WL_%=:\n\t" \
        "mbarrier.try_wait.parity.acquire.cta.shared::cta.b64 P1, [%0], %1, 0x989680;\n\t" \
        "@P1 bra.uni WD_%=;\n\t" \
        "bra.uni WL_%=;\n\t" \
        "WD_%=:\n\t}" :: "r"(_mb), "r"(_ph) : "memory"); \
} while (0)
#define BULK_LD(dst, src, bytes, mb) \
    asm volatile("cp.async.bulk.shared::cluster.global.mbarrier::complete_tx::bytes " \
                 "[%0], [%1], %2, [%3];" \
                 :: "r"((uint32_t)(dst)), "l"(src), "r"((uint32_t)(bytes)), \
                    "r"((uint32_t)(mb)) : "memory")

// ---------------------------------------------------------------------------
// init small accumulators
// ---------------------------------------------------------------------------
__global__ void init_kernel() {
    int i = blockIdx.x * blockDim.x + threadIdx.x;
    if (i < 131072) g_scratch[OFF_CTX + i] = 0.0f;
    if (i < 2048)   g_scratch[OFF_KCS + i] = 0.0f;
    if (i < 64)     g_scratch[OFF_KMAX + i] = -INFINITY;
}

// ---------------------------------------------------------------------------
// tiled offset helper
// ---------------------------------------------------------------------------
__device__ __forceinline__ size_t tiled_off(int R, int k) {
    return (size_t)((R >> 7) * 32 + (k >> 5)) * CHUNK_H + (R & 127) * 40 +
           (k & 31);
}

// ---------------------------------------------------------------------------
// fp16 split into tiled layout (4 elements per thread, same chunk)
// ---------------------------------------------------------------------------
__global__ void split_kernel(const float* __restrict__ s, __half* __restrict__ hi,
                             __half* __restrict__ lo, int n) {
    int i = (blockIdx.x * blockDim.x + threadIdx.x) * 4;
    if (i >= n) return;
    float4 v = *(const float4*)(s + i);
    float vv[4] = {v.x, v.y, v.z, v.w};
    __half h[4], l[4];
#pragma unroll
    for (int j = 0; j < 4; j++) {
        h[j] = __float2half_rn(vv[j]);
        l[j] = __float2half_rn(vv[j] - __half2float(h[j]));
    }
    int R = i >> 10, k = i & 1023;
    size_t off = tiled_off(R, k);
    __half2* hp = (__half2*)(hi + off);
    hp[0] = __halves2half2(h[0], h[1]);
    hp[1] = __halves2half2(h[2], h[3]);
    __half2* lp = (__half2*)(lo + off);
    lp[0] = __halves2half2(l[0], l[1]);
    lp[1] = __halves2half2(l[2], l[3]);
}

// fp16 split + transpose for weights: W[k][n] -> tiled[n][k]
__global__ void splitT_kernel(const float* __restrict__ W, __half* __restrict__ hiT,
                              __half* __restrict__ loT) {
    __shared__ float t[32][33];
    int tx = threadIdx.x, ty = threadIdx.y;
    int bn = blockIdx.x * 32, bk = blockIdx.y * 32;
    for (int j = ty; j < 32; j += 8)
        t[j][tx] = W[(size_t)(bk + j) * DIM_ + bn + tx];
    __syncthreads();
    for (int j = ty; j < 32; j += 8) {
        float v = t[tx][j];
        __half h = __float2half_rn(v);
        __half l = __float2half_rn(v - __half2float(h));
        size_t off = tiled_off(bn + j, bk + tx);
        hiT[off] = h;
        loT[off] = l;
    }
}

// ---------------------------------------------------------------------------
// fp16 HMMA m16n8k16 wrapper
// ---------------------------------------------------------------------------
__device__ __forceinline__ void mma_f16(float* c, const uint32_t* a,
                                        uint32_t b0, uint32_t b1) {
    asm volatile(
        "mma.sync.aligned.m16n8k16.row.col.f32.f16.f16.f32 "
        "{%0,%1,%2,%3}, {%4,%5,%6,%7}, {%8,%9}, {%0,%1,%2,%3};"
        : "+f"(c[0]), "+f"(c[1]), "+f"(c[2]), "+f"(c[3])
        : "r"(a[0]), "r"(a[1]), "r"(a[2]), "r"(a[3]), "r"(b0), "r"(b1));
}

// ---------------------------------------------------------------------------
// atomic float max via CAS
// ---------------------------------------------------------------------------
__device__ __forceinline__ void atomicMaxFloat(float* addr, float val) {
    int old = __float_as_int(*addr);
    while (__int_as_float(old) < val) {
        int assumed = old;
        old = atomicCAS((int*)addr, assumed, __float_as_int(val));
        if (old == assumed) break;
    }
}

// ---------------------------------------------------------------------------
// HMMA GEMM, cp.async.bulk 2-stage pipeline (4 bulk ops/stage) +
// optional fused Performer feature epilogue.
// MODE 0: C = A@W + bias -> out (fp32, R x 1024)
// MODE 1: q-feature epilogue -> out = QF[(bh*N+n)*32+m]
// MODE 2: k-feature epilogue -> out = TK (dd - diag); atomicMax kmax_g[bh]
// 2 stages x 40960 B keeps 2 CTAs/SM — load-latency hiding via co-resident CTA.
// ---------------------------------------------------------------------------
#define TILE_H   5120                  // halves per tile (128*40)
#define TILE_B2  (TILE_H * 2)          // bytes per tile (10240)
#define STAGE_H  (4 * TILE_H)          // halves per stage
#define STAGE_B  (STAGE_H * 2)         // bytes per stage (40960)
#define SMEM0    (2 * STAGE_B)         // 81920
#define SMEM_F   (2 * STAGE_B + 8704)  // + projS 32*68 floats
#define NST 32                         // K / BK

template <int MODE>
__global__ void __launch_bounds__(256)
gemm_hmma_kernel(const __half* __restrict__ Ahi, const __half* __restrict__ Alo,
                 const __half* __restrict__ Bhi, const __half* __restrict__ Blo,
                 const float* __restrict__ bias, float* __restrict__ out,
                 const float* __restrict__ proj, float* __restrict__ kmax_g) {
    extern __shared__ __align__(16) __half sm[];
    const uint32_t smb = smem_u32(sm);
    __shared__ __align__(8) uint64_t mbars[2];
    __shared__ float s_hm[8];
    const uint32_t mb0 = smem_u32(&mbars[0]);
    const uint32_t mb1 = smem_u32(&mbars[1]);

    const int tid = threadIdx.x;
    const int lane = tid & 31, wid = tid >> 5;
    const int wm = wid & 3;            // warp m index (x32 rows)
    const int wn = wid >> 2;           // warp n index (x64 cols)
    const int m0 = blockIdx.y * 128, n0 = blockIdx.x * 128;
    const int grp = lane >> 2;         // 0..7
    const int tig = lane & 3;          // 0..3

    const size_t aBase = (size_t)(m0 >> 7) * RBLK_H;
    const size_t bBase = (size_t)(n0 >> 7) * RBLK_H;

    float* projS = (float*)(sm + 2 * STAGE_H);   // [m][d] stride 68
    if (MODE != 0) {
        for (int i = tid; i < 2048; i += 256) {
            int mrow = i >> 6, d = i & 63;
            projS[mrow * 68 + d] = proj[i];
        }
    }

    if (tid == 0) { MBAR_INIT(mb0, 1); MBAR_INIT(mb1, 1); }
    __syncthreads();

    float acc[2][8][4];
#pragma unroll
    for (int mi = 0; mi < 2; mi++)
#pragma unroll
        for (int ni = 0; ni < 8; ni++)
#pragma unroll
            for (int j = 0; j < 4; j++) acc[mi][ni][j] = 0.0f;

    auto issue_stage = [&](int sb, int s) {
        if (tid == 0) {
            uint32_t mb = sb ? mb1 : mb0;
            MBAR_EXPECT_TX(mb, STAGE_B);
            uint32_t d = smb + sb * STAGE_B;
            size_t co = (size_t)s * CHUNK_H;
            BULK_LD(d, Ahi + aBase + co, TILE_B2, mb);
            BULK_LD(d + TILE_B2, Alo + aBase + co, TILE_B2, mb);
            BULK_LD(d + 2 * TILE_B2, Bhi + bBase + co, TILE_B2, mb);
            BULK_LD(d + 3 * TILE_B2, Blo + bBase + co, TILE_B2, mb);
        }
    };

    issue_stage(0, 0);

    for (int s = 0; s < NST; s++) {
        if (s + 1 < NST) issue_stage((s + 1) & 1, s + 1);
        MBAR_WAIT((s & 1) ? mb1 : mb0, (s >> 1) & 1);

        const uint32_t* wAh = (const uint32_t*)(sm + (s & 1) * STAGE_H);
        const uint32_t* wAl = wAh + TILE_H / 2;
        const uint32_t* wBh = wAh + TILE_H;
        const uint32_t* wBl = wAh + 3 * TILE_H / 2;

#pragma unroll
        for (int ks = 0; ks < 2; ks++) {
            const int kw = ks * 8 + tig;
            uint32_t ah[2][4], al[2][4];
#pragma unroll
            for (int mi = 0; mi < 2; mi++) {
                int rr = wm * 32 + mi * 16 + grp;
                ah[mi][0] = wAh[rr * 20 + kw];
                ah[mi][1] = wAh[(rr + 8) * 20 + kw];
                ah[mi][2] = wAh[rr * 20 + kw + 4];
                ah[mi][3] = wAh[(rr + 8) * 20 + kw + 4];
                al[mi][0] = wAl[rr * 20 + kw];
                al[mi][1] = wAl[(rr + 8) * 20 + kw];
                al[mi][2] = wAl[rr * 20 + kw + 4];
                al[mi][3] = wAl[(rr + 8) * 20 + kw + 4];
            }
#pragma unroll
            for (int nj = 0; nj < 8; nj++) {
                int cc = wn * 64 + nj * 8 + grp;
                uint32_t bh0 = wBh[cc * 20 + kw];
                uint32_t bh1 = wBh[cc * 20 + kw + 4];
                uint32_t bl0 = wBl[cc * 20 + kw];
                uint32_t bl1 = wBl[cc * 20 + kw + 4];
#pragma unroll
                for (int mi = 0; mi < 2; mi++) {
                    mma_f16(acc[mi][nj], ah[mi], bh0, bh1);
                    mma_f16(acc[mi][nj], ah[mi], bl0, bl1);
                    mma_f16(acc[mi][nj], al[mi], bh0, bh1);
                }
            }
        }
        __syncthreads();
    }

    if (MODE == 0) {
#pragma unroll
        for (int ni = 0; ni < 8; ni++) {
            int col = n0 + wn * 64 + ni * 8 + tig * 2;
            float2 bv = *(const float2*)&bias[col];
#pragma unroll
            for (int mi = 0; mi < 2; mi++) {
                int row = m0 + wm * 32 + mi * 16 + grp;
                float2 c0 = make_float2(acc[mi][ni][0] + bv.x,
                                        acc[mi][ni][1] + bv.y);
                float2 c1 = make_float2(acc[mi][ni][2] + bv.x,
                                        acc[mi][ni][3] + bv.y);
                *(float2*)&out[(size_t)row * DIM_ + col] = c0;
                *(float2*)&out[(size_t)(row + 8) * DIM_ + col] = c1;
            }
        }
        return;
    }

    // -------- fused feature epilogue (MODE 1 = q, MODE 2 = k) --------
    float* Cs = (float*)sm;   // 128 x 132 fp32 tile, reuses stage area
#pragma unroll
    for (int ni = 0; ni < 8; ni++) {
        int col = wn * 64 + ni * 8 + tig * 2;
        float2 bv = *(const float2*)&bias[n0 + col];
#pragma unroll
        for (int mi = 0; mi < 2; mi++) {
            int row = wm * 32 + mi * 16 + grp;
            Cs[row * 132 + col] = acc[mi][ni][0] + bv.x;
            Cs[row * 132 + col + 1] = acc[mi][ni][1] + bv.y;
            Cs[(row + 8) * 132 + col] = acc[mi][ni][2] + bv.x;
            Cs[(row + 8) * 132 + col + 1] = acc[mi][ni][3] + bv.y;
        }
    }
    __syncthreads();

    const int hh = wid & 1;                    // head within tile
    const int head = blockIdx.x * 2 + hh;      // global head
    const int b = m0 >> 12;                    // batch (constant per block)
    const int bh = b * H_ + head;
    const int r0 = (wid >> 1) * 32;            // 4 warp-groups x 32 rows
    const float4* pr = (const float4*)&projS[lane * 68];
    float kmaxw = -INFINITY;

    for (int rr = r0; rr < r0 + 32; rr++) {
        const float* qrow = &Cs[rr * 132 + hh * 64];
        float q0 = qrow[lane], q1 = qrow[lane + 32];
        float ss = fmaf(q0, q0, q1 * q1);
#pragma unroll
        for (int off = 16; off > 0; off >>= 1)
            ss += __shfl_xor_sync(0xffffffffu, ss, off);

        const float4* qp = (const float4*)qrow;
        float accd = 0.0f;
#pragma unroll
        for (int d4 = 0; d4 < 16; d4++) {
            float4 p = pr[d4];
            float4 qd = qp[d4];
            accd = fmaf(p.x, qd.x, accd);
            accd = fmaf(p.y, qd.y, accd);
            accd = fmaf(p.z, qd.z, accd);
            accd = fmaf(p.w, qd.w, accd);
        }
        float dd = NORMALIZER * accd;          // data_dash at m = lane
        float diag = HALF_NORM2 * ss;

        float wmax = dd;
#pragma unroll
        for (int off = 16; off > 0; off >>= 1)
            wmax = fmaxf(wmax, __shfl_xor_sync(0xffffffffu, wmax, off));

        const int n = (m0 + rr) & 4095;
        const size_t idx = ((size_t)bh * N_ + n) * M_ + lane;
        if (MODE == 1) {
            out[idx] = RATIO * (__expf(dd - diag - wmax) + EPS_);
        } else {
            out[idx] = dd - diag;
            kmaxw = fmaxf(kmaxw, wmax);
        }
    }

    if (MODE == 2) {
        if (lane == 0) s_hm[wid] = kmaxw;
        __syncthreads();
        if (tid < 2) {
            float m4 = fmaxf(fmaxf(s_hm[tid], s_hm[tid + 2]),
                             fmaxf(s_hm[tid + 4], s_hm[tid + 6]));
            atomicMaxFloat(&kmax_g[b * H_ + blockIdx.x * 2 + tid], m4);
        }
    }
}

// ---------------------------------------------------------------------------
// Context + k_cumsum (__expf in hot loop)
// ---------------------------------------------------------------------------
__global__ void __launch_bounds__(256)
ctx_kernel(const unsigned char* __restrict__ mask) {
    __shared__ __align__(16) float kf_s[16][32];
    __shared__ __align__(16) float v_s[16][64];
    const int tid = threadIdx.x;
    const int bh = blockIdx.x >> 3, chunk = blockIdx.x & 7;
    const int b = bh >> 4, h = bh & 15;
    const float kmax = g_scratch[OFF_KMAX + bh];
    const int m = tid >> 3, eb = (tid & 7) * 8;

    float acc[8];
#pragma unroll
    for (int j = 0; j < 8; j++) acc[j] = 0.0f;
    float kcsl = 0.0f;

    const float* tk = g_scratch + OFF_TK + (size_t)bh * N_ * M_;
    const float* V = g_scratch + OFF_V;

    const int base = chunk * 512;
    for (int t0 = base; t0 < base + 512; t0 += 16) {
#pragma unroll
        for (int j = 0; j < 2; j++) {
            int lin = tid * 2 + j;
            int i = lin >> 5, mm = lin & 31;
            float tv = tk[(size_t)(t0 + i) * M_ + mm];
            kf_s[i][mm] = RATIO * (__expf(tv - kmax) + EPS_);
        }
        {
            int i = tid >> 4, e4 = (tid & 15) * 4;
            int n = t0 + i;
            float4 v4 =
                *(const float4*)&V[(size_t)(b * N_ + n) * DIM_ + h * DH_ + e4];
            if (mask[b * N_ + n]) v4 = make_float4(0.f, 0.f, 0.f, 0.f);
            *(float4*)&v_s[i][e4] = v4;
        }
        __syncthreads();
#pragma unroll
        for (int i = 0; i < 16; i++) {
            float kfm = kf_s[i][m];
            kcsl += kfm;
#pragma unroll
            for (int j = 0; j < 8; j++)
                acc[j] = fmaf(kfm, v_s[i][eb + j], acc[j]);
        }
        __syncthreads();
    }

    float* ctx = g_scratch + OFF_CTX + (size_t)bh * (M_ * DH_);
#pragma unroll
    for (int j = 0; j < 8; j++) atomicAdd(&ctx[m * DH_ + eb + j], acc[j]);
    if ((tid & 7) == 0) atomicAdd(&g_scratch[OFF_KCS + bh * M_ + m], kcsl);
}

// ---------------------------------------------------------------------------
// Output head: smem broadcast (no shfl chain); writes fp16 hi/lo tiled
// ---------------------------------------------------------------------------
__global__ void __launch_bounds__(256)
outhead_kernel(__half* __restrict__ Ohi, __half* __restrict__ Olo) {
    __shared__ float ctx_s[M_ * DH_];
    __shared__ float kcs_s[M_];
    __shared__ float qs[256];
    const int tid = threadIdx.x;
    const int bh = blockIdx.x >> 3, chunk = blockIdx.x & 7;
    const int b = bh >> 4, h = bh & 15;
    for (int i = tid; i < M_ * DH_; i += 256)
        ctx_s[i] = g_scratch[OFF_CTX + (size_t)bh * (M_ * DH_) + i];
    if (tid < M_) kcs_s[tid] = g_scratch[OFF_KCS + bh * M_ + tid];
    __syncthreads();

    const int w = tid >> 5, lane = tid & 31;
    float* qw = &qs[w * 32];
    const float* qf = g_scratch + OFF_QF + (size_t)bh * N_ * M_;

    for (int rr = 0; rr < 64; rr++) {
        int n = chunk * 512 + w * 64 + rr;
        qw[lane] = qf[(size_t)n * M_ + lane];
        __syncwarp();
        float acc0 = 0.0f, acc1 = 0.0f, den = 0.0f;
#pragma unroll
        for (int mm = 0; mm < 32; mm++) {
            float qm = qw[mm];
            acc0 = fmaf(qm, ctx_s[mm * DH_ + lane], acc0);
            acc1 = fmaf(qm, ctx_s[mm * DH_ + 32 + lane], acc1);
            den = fmaf(qm, kcs_s[mm], den);
        }
        __syncwarp();
        float dinv = 1.0f / den;
        float v0 = acc0 * dinv, v1 = acc1 * dinv;
        __half h0 = __float2half_rn(v0);
        __half h1 = __float2half_rn(v1);
        __half l0 = __float2half_rn(v0 - __half2float(h0));
        __half l1 = __float2half_rn(v1 - __half2float(h1));
        int R = b * N_ + n;
        size_t o1 = tiled_off(R, h * DH_ + lane);
        size_t o2 = tiled_off(R, h * DH_ + 32 + lane);
        Ohi[o1] = h0;
        Ohi[o2] = h1;
        Olo[o1] = l0;
        Olo[o2] = l1;
    }
}

// ---------------------------------------------------------------------------
// launch
// ---------------------------------------------------------------------------
extern "C" void kernel_launch(void* const* d_in, const int* in_sizes, int n_in,
                              void* d_out, int out_size) {
    (void)in_sizes; (void)n_in; (void)out_size;
    const float* x = (const float*)d_in[0];
    const unsigned char* mask = (const unsigned char*)d_in[1];
    const float* proj = (const float*)d_in[2];
    const float* Wq = (const float*)d_in[3];
    const float* bq = (const float*)d_in[4];
    const float* Wk = (const float*)d_in[5];
    const float* bk = (const float*)d_in[6];
    const float* Wv = (const float*)d_in[7];
    const float* bv = (const float*)d_in[8];
    const float* Wo = (const float*)d_in[9];
    const float* bo = (const float*)d_in[10];

    float* scratch = nullptr;
    cudaGetSymbolAddress((void**)&scratch, g_scratch);
    __half* hs = nullptr;
    cudaGetSymbolAddress((void**)&hs, g_half);

    cudaFuncSetAttribute(gemm_hmma_kernel<0>,
                         cudaFuncAttributeMaxDynamicSharedMemorySize, SMEM0);
    cudaFuncSetAttribute(gemm_hmma_kernel<1>,
                         cudaFuncAttributeMaxDynamicSharedMemorySize, SMEM_F);
    cudaFuncSetAttribute(gemm_hmma_kernel<2>,
                         cudaFuncAttributeMaxDynamicSharedMemorySize, SMEM_F);

    dim3 tg(32, 32), tb(32, 8);
    dim3 gg(DIM_ / 128, R_ / 128);   // (8, 128)

    init_kernel<<<512, 256>>>();
    split_kernel<<<R_ * DIM_ / 4 / 256, 256>>>(x, hs + HX_HI,
                                               hs + HX_LO, R_ * DIM_);
    splitT_kernel<<<tg, tb>>>(Wq, hs + HW_BASE + 0 * W_HALVES,
                              hs + HW_BASE + 1 * W_HALVES);
    splitT_kernel<<<tg, tb>>>(Wk, hs + HW_BASE + 2 * W_HALVES,
                              hs + HW_BASE + 3 * W_HALVES);
    splitT_kernel<<<tg, tb>>>(Wv, hs + HW_BASE + 4 * W_HALVES,
                              hs + HW_BASE + 5 * W_HALVES);

    // Q GEMM + fused q-feature
    gemm_hmma_kernel<1><<<gg, 256, SMEM_F>>>(
        hs + HX_HI, hs + HX_LO, hs + HW_BASE + 0 * W_HALVES,
        hs + HW_BASE + 1 * W_HALVES, bq, scratch + OFF_QF, proj, nullptr);
    // K GEMM + fused k-feature
    gemm_hmma_kernel<2><<<gg, 256, SMEM_F>>>(
        hs + HX_HI, hs + HX_LO, hs + HW_BASE + 2 * W_HALVES,
        hs + HW_BASE + 3 * W_HALVES, bk, scratch + OFF_TK, proj,
        scratch + OFF_KMAX);
    // V GEMM (plain)
    gemm_hmma_kernel<0><<<gg, 256, SMEM0>>>(
        hs + HX_HI, hs + HX_LO, hs + HW_BASE + 4 * W_HALVES,
        hs + HW_BASE + 5 * W_HALVES, bv, scratch + OFF_V, nullptr, nullptr);

    ctx_kernel<<<64 * 8, 256>>>(mask);
    outhead_kernel<<<64 * 8, 256>>>(hs + HA_HI, hs + HA_LO);

    splitT_kernel<<<tg, tb>>>(Wo, hs + HW_BASE + 6 * W_HALVES,
                              hs + HW_BASE + 7 * W_HALVES);
    // O GEMM (plain) -> d_out
    gemm_hmma_kernel<0><<<gg, 256, SMEM0>>>(
        hs + HA_HI, hs + HA_LO, hs + HW_BASE + 6 * W_HALVES,
        hs + HW_BASE + 7 * W_HALVES, bo, (float*)d_out, nullptr, nullptr);
}